// round 1
// baseline (speedup 1.0000x reference)
#include <cuda_runtime.h>

#define NV 576
#define MROWS 144
#define ROW_DEG 15
#define BATCH 256
#define ITERS 3

// Compact column indices of H: 15 sorted column ids per check row.
__device__ short g_cols[MROWS * ROW_DEG];

// One warp per row: ballot + prefix-popcount -> column ids in ascending order
// (matches jax.lax.top_k lowest-index tie-break for the argmin).
__global__ void prep_kernel(const float* __restrict__ H) {
    int m = blockIdx.x;
    int lane = threadIdx.x;
    int count = 0;
    for (int base = 0; base < NV; base += 32) {
        float v = H[m * NV + base + lane];
        unsigned ball = __ballot_sync(0xffffffffu, v != 0.0f);
        int pre = __popc(ball & ((1u << lane) - 1u));
        if (v != 0.0f) {
            int slot = count + pre;
            if (slot < ROW_DEG) g_cols[m * ROW_DEG + slot] = (short)(base + lane);
        }
        count += __popc(ball);
    }
}

__global__ __launch_bounds__(192) void ldpc_kernel(
    const float* __restrict__ r,
    const float* __restrict__ alpha,
    const float* __restrict__ beta,
    float* __restrict__ out)
{
    __shared__ float r_s[NV];
    __shared__ float sumE[2][NV];
    __shared__ float E_s[MROWS * ROW_DEG];
    __shared__ short cols_s[MROWS * ROW_DEG];

    const int b = blockIdx.x;
    const int tid = threadIdx.x;
    const float* rb = r + b * NV;

    for (int i = tid; i < NV; i += blockDim.x) {
        r_s[i] = rb[i];
        sumE[0][i] = 0.0f;
    }
    for (int i = tid; i < MROWS * ROW_DEG; i += blockDim.x) {
        E_s[i] = 0.0f;
        cols_s[i] = g_cols[i];
    }
    __syncthreads();

    int cur = 0;
    for (int it = 0; it < ITERS; ++it) {
        const float al = alpha[it];
        const float be = beta[it];
        const int nxt = cur ^ 1;

        for (int i = tid; i < NV; i += blockDim.x) sumE[nxt][i] = 0.0f;
        __syncthreads();

        if (tid < MROWS) {
            float sg[ROW_DEG];
            short cc[ROW_DEG];
            float min1 = 3.4e38f, min2 = 3.4e38f;
            int j1 = 0;
            float s = 1.0f;
            #pragma unroll
            for (int j = 0; j < ROW_DEG; ++j) {
                short c = cols_s[tid * ROW_DEG + j];
                float e = E_s[tid * ROW_DEG + j];
                // iter 0: sumE=0, E=0  ->  M = r (== H*r at the live positions)
                float Mv = r_s[c] + sumE[cur][c] - e;
                float g = (Mv > 0.0f) ? 1.0f : ((Mv < 0.0f) ? -1.0f : 0.0f);
                s *= g;
                float av = fabsf(Mv);
                if (av < min1) { min2 = min1; min1 = av; j1 = j; }
                else if (av < min2) { min2 = av; }
                sg[j] = g;
                cc[j] = c;
            }
            #pragma unroll
            for (int j = 0; j < ROW_DEG; ++j) {
                float Eabs = (j == j1) ? min2 : min1;
                float Ej = al * s * sg[j] * fmaxf(0.0f, Eabs - be);
                E_s[tid * ROW_DEG + j] = Ej;
                atomicAdd(&sumE[nxt][cc[j]], Ej);
            }
        }
        __syncthreads();
        cur = nxt;
    }

    float* ob = out + b * NV;
    for (int i = tid; i < NV; i += blockDim.x)
        ob[i] = r_s[i] + sumE[cur][i];
}

extern "C" void kernel_launch(void* const* d_in, const int* in_sizes, int n_in,
                              void* d_out, int out_size)
{
    const float* r     = (const float*)d_in[0];   // [256, 576]
    const float* H     = (const float*)d_in[1];   // [144, 576]
    const float* alpha = (const float*)d_in[2];   // [3]
    const float* beta  = (const float*)d_in[3];   // [3]
    float* out = (float*)d_out;                   // [256, 576]

    prep_kernel<<<MROWS, 32>>>(H);
    ldpc_kernel<<<BATCH, 192>>>(r, alpha, beta, out);
}

// round 2
// speedup vs baseline: 1.2786x; 1.2786x over previous
#include <cuda_runtime.h>

#define NV 576
#define MROWS 144
#define ROW_DEG 15
#define BATCH 256
#define ITERS 3
#define NBUF (ITERS + 1)
#define BPC 2                    // batch elements per CTA
#define THREADS (BPC * MROWS)    // 288

// Compact column indices of H: 15 sorted column ids per check row.
__device__ short g_cols[MROWS * ROW_DEG];

// One warp per row: ballot + prefix-popcount -> column ids in ascending order
// (matches jax.lax.top_k lowest-index tie-break for the argmin).
__global__ void prep_kernel(const float* __restrict__ H) {
    int m = blockIdx.x;
    int lane = threadIdx.x;
    int count = 0;
    for (int base = 0; base < NV; base += 32) {
        float v = H[m * NV + base + lane];
        unsigned ball = __ballot_sync(0xffffffffu, v != 0.0f);
        int pre = __popc(ball & ((1u << lane) - 1u));
        if (v != 0.0f) {
            int slot = count + pre;
            if (slot < ROW_DEG) g_cols[m * ROW_DEG + slot] = (short)(base + lane);
        }
        count += __popc(ball);
    }
}

__global__ __launch_bounds__(THREADS) void ldpc_kernel(
    const float* __restrict__ r,
    const float* __restrict__ alpha,
    const float* __restrict__ beta,
    float* __restrict__ out)
{
    // sumE buffers pre-initialized to r: buf[k][c] ends as r[c] + sum_rows E_k.
    __shared__ float sumE[BPC][NBUF][NV];

    const int tid  = threadIdx.x;
    const int half = tid / MROWS;          // which batch element within the CTA
    const int row  = tid - half * MROWS;   // check row 0..143
    const int b    = blockIdx.x * BPC + half;

    // alpha/beta into registers (uniform, L1-hit)
    float alv[ITERS], bev[ITERS];
    #pragma unroll
    for (int k = 0; k < ITERS; ++k) { alv[k] = alpha[k]; bev[k] = beta[k]; }

    // Broadcast r into all NBUF buffers
    const float* rb = r + b * NV;
    #pragma unroll
    for (int i = row; i < NV; i += MROWS) {
        float v = rb[i];
        #pragma unroll
        for (int k = 0; k < NBUF; ++k) sumE[half][k][i] = v;
    }

    // This row's column indices -> registers (loop-invariant)
    short cc[ROW_DEG];
    #pragma unroll
    for (int j = 0; j < ROW_DEG; ++j) cc[j] = g_cols[row * ROW_DEG + j];

    // This row's extrinsic messages live in registers
    float Ev[ROW_DEG];
    #pragma unroll
    for (int j = 0; j < ROW_DEG; ++j) Ev[j] = 0.0f;

    __syncthreads();

    #pragma unroll
    for (int it = 0; it < ITERS; ++it) {
        float sg[ROW_DEG];
        float min1 = 3.4e38f, min2 = 3.4e38f;
        int j1 = 0;
        float s = 1.0f;

        #pragma unroll
        for (int j = 0; j < ROW_DEG; ++j) {
            // M_j = r[c] + sum_E[c] - E_j  (r already folded into buffer)
            float Mv = sumE[half][it][cc[j]] - Ev[j];
            float g = (Mv > 0.0f) ? 1.0f : ((Mv < 0.0f) ? -1.0f : 0.0f);
            s *= g;
            float av = fabsf(Mv);
            if (av < min1) { min2 = min1; min1 = av; j1 = j; }
            else if (av < min2) { min2 = av; }
            sg[j] = g;
        }

        const float coef = alv[it] * s;
        const float m1c = fmaxf(0.0f, min1 - bev[it]);
        const float m2c = fmaxf(0.0f, min2 - bev[it]);

        #pragma unroll
        for (int j = 0; j < ROW_DEG; ++j) {
            float Ej = coef * sg[j] * ((j == j1) ? m2c : m1c);
            Ev[j] = Ej;
            atomicAdd(&sumE[half][it + 1][cc[j]], Ej);
        }
        __syncthreads();
    }

    // out = r + sum_rows E_last  == sumE[ITERS]
    float* ob = out + b * NV;
    #pragma unroll
    for (int i = row; i < NV; i += MROWS)
        ob[i] = sumE[half][ITERS][i];
}

extern "C" void kernel_launch(void* const* d_in, const int* in_sizes, int n_in,
                              void* d_out, int out_size)
{
    const float* r     = (const float*)d_in[0];   // [256, 576]
    const float* H     = (const float*)d_in[1];   // [144, 576]
    const float* alpha = (const float*)d_in[2];   // [3]
    const float* beta  = (const float*)d_in[3];   // [3]
    float* out = (float*)d_out;                   // [256, 576]

    prep_kernel<<<MROWS, 32>>>(H);
    ldpc_kernel<<<BATCH / BPC, THREADS>>>(r, alpha, beta, out);
}